// round 16
// baseline (speedup 1.0000x reference)
#include <cuda_runtime.h>
#include <cuda_fp16.h>
#include <cstdint>

// Problem dims (fixed)
#define FDIM 1024
#define CDIM 128
#define BDIM 2048

#define BM 16
#define BN 128
#define THREADS 512

// ---------------- scratch ----------------
// Blocked, pre-swizzled: byte offset = kc*32768 + c*256 + ((kk*2) ^ ((c&7)<<4))
__device__ __align__(16) __half g_b[CDIM * FDIM];
__device__ uint32_t g_done = 0;   // classes published
__device__ uint32_t g_exit = 0;   // CTAs exited (for replay-safe reset)

// ---------------- helpers ----------------
__device__ __forceinline__ uint32_t smem_u32(const void* p) {
    uint32_t a;
    asm("{ .reg .u64 t; cvta.to.shared.u64 t, %1; cvt.u32.u64 %0, t; }" : "=r"(a) : "l"(p));
    return a;
}
__device__ __forceinline__ uint32_t swz256(uint32_t row, uint32_t colByte) {
    return row * 256u + (colByte ^ ((row & 7u) << 4));
}
__device__ __forceinline__ uint32_t ld_acq(const uint32_t* p) {
    uint32_t v;
    asm volatile("ld.acquire.gpu.u32 %0, [%1];" : "=r"(v) : "l"(p) : "memory");
    return v;
}

#define MBAR_INIT(mb, n)  asm volatile("mbarrier.init.shared.b64 [%0], %1;" :: "r"((uint32_t)(mb)), "r"((uint32_t)(n)) : "memory")
#define MBAR_EXPECT_TX(mb, bytes) \
    asm volatile("mbarrier.arrive.expect_tx.shared.b64 _, [%0], %1;" :: "r"((uint32_t)(mb)), "r"((uint32_t)(bytes)) : "memory")
#define BULK_G2S(dst, src, bytes, mb) \
    asm volatile("cp.async.bulk.shared::cta.global.mbarrier::complete_tx::bytes [%0], [%1], %2, [%3];" \
                 :: "r"((uint32_t)(dst)), "l"(src), "r"((uint32_t)(bytes)), "r"((uint32_t)(mb)) : "memory")
#define MBAR_WAIT(mb, ph) do {                                                   \
    uint32_t _m = (uint32_t)(mb), _p = (uint32_t)(ph), _d;                       \
    asm volatile("{\n\t.reg .pred p;\n\t"                                        \
        "mbarrier.try_wait.parity.acquire.cta.shared::cta.b64 p, [%1], %2;\n\t"  \
        "selp.b32 %0, 1, 0, p;\n\t}" : "=r"(_d) : "r"(_m), "r"(_p) : "memory");  \
    if (!_d) {                                                                   \
        asm volatile("{\n\t.reg .pred P1;\n\t"                                   \
            "W_%=:\n\t"                                                          \
            "mbarrier.try_wait.parity.acquire.cta.shared::cta.b64 P1, [%0], %1, 0x989680;\n\t" \
            "@P1 bra.uni D_%=;\n\t"                                              \
            "bra.uni W_%=;\n\t"                                                  \
            "D_%=:\n\t}" :: "r"(_m), "r"(_p) : "memory");                        \
    }                                                                            \
} while (0)

#define LDMATRIX_X4(r0, r1, r2, r3, addr)                                        \
    asm volatile("ldmatrix.sync.aligned.m8n8.x4.shared.b16 {%0,%1,%2,%3}, [%4];" \
                 : "=r"(r0), "=r"(r1), "=r"(r2), "=r"(r3) : "r"(addr))

#define MMA_F16(d, a, b)                                                         \
    asm volatile("mma.sync.aligned.m16n8k16.row.col.f32.f16.f16.f32 "            \
                 "{%0,%1,%2,%3}, {%4,%5,%6,%7}, {%8,%9}, {%0,%1,%2,%3};"         \
                 : "+f"((d)[0]), "+f"((d)[1]), "+f"((d)[2]), "+f"((d)[3])        \
                 : "r"((a)[0]), "r"((a)[1]), "r"((a)[2]), "r"((a)[3]),           \
                   "r"((b)[0]), "r"((b)[1]))

// ---------------------------------------------------------------------------
// Fused kernel. 128 CTAs x 512 threads, 1 CTA/SM (all co-resident).
// CTA i: warp 0 additionally computes softmax(weight[i,:]) -> g_b (hidden
// under the CTA's x-load phase); tid0 spins for all 128 classes before the
// first B bulk load. Mainloop = R15 (resident A, kh-split, buffer recycle).
// ---------------------------------------------------------------------------
#define MBAR_BASE 0                 // 5 x 8B mbarriers
#define A_OFF 1024                  // 32KB full A (8 chunks x 4KB)
#define B_OFF (A_OFF + 32768)       // 5 x 32KB B buffers
#define RED_OFF (B_OFF + 5 * 32768) // 8KB reduce buffer
#define SMEM_TOTAL (RED_OFF + 8192) // 205824

__global__ void __launch_bounds__(THREADS) fused_kernel(const float* __restrict__ x,
                                                        const float* __restrict__ w,
                                                        float* __restrict__ out) {
    extern __shared__ char smem[];
    const uint32_t sbase = smem_u32(smem);
    const int tid  = threadIdx.x;
    const int warp = tid >> 5;
    const int lane = tid & 31;
    const int kh   = warp >> 3;    // 0: chunks 0-3, 1: chunks 4-7
    const int nw   = warp & 7;     // cols [nw*16, +16)

    const int mtile = (int)blockIdx.x;   // 0..127 (also = class this CTA preps)
    const char* gb = reinterpret_cast<const char*>(g_b);

    // ---- FIRST: all x loads, maximal MLP ----
    const float* xbase = x + (size_t)mtile * BM * FDIM;
    const uint32_t xrow = (uint32_t)tid >> 5;    // 0..15
    const uint32_t xc4  = (uint32_t)tid & 31;
    float4 xv[8];
#pragma unroll
    for (int j = 0; j < 8; j++)
        xv[j] = *reinterpret_cast<const float4*>(
            xbase + (size_t)xrow * FDIM + j * 128 + xc4 * 4);

    // ---- warp 0: softmax of class `mtile` -> g_b (blocked pre-swizzled) ----
    if (warp == 0) {
        const float* row = w + (size_t)mtile * FDIM;
        float4 v[8];
        float m = -1e30f;
#pragma unroll
        for (int j = 0; j < 8; j++) {
            v[j] = *reinterpret_cast<const float4*>(row + j * 128 + lane * 4);
            m = fmaxf(m, fmaxf(fmaxf(v[j].x, v[j].y), fmaxf(v[j].z, v[j].w)));
        }
#pragma unroll
        for (int s = 16; s > 0; s >>= 1) m = fmaxf(m, __shfl_xor_sync(0xffffffffu, m, s));
        float sum = 0.0f;
#pragma unroll
        for (int j = 0; j < 8; j++) {
            v[j].x = __expf(v[j].x - m); v[j].y = __expf(v[j].y - m);
            v[j].z = __expf(v[j].z - m); v[j].w = __expf(v[j].w - m);
            sum += (v[j].x + v[j].y) + (v[j].z + v[j].w);
        }
#pragma unroll
        for (int s = 16; s > 0; s >>= 1) sum += __shfl_xor_sync(0xffffffffu, sum, s);
        const float inv = 1.0f / sum;

        char* gwr = reinterpret_cast<char*>(g_b);
#pragma unroll
        for (int j = 0; j < 8; j++) {
            __half2 h01 = __floats2half2_rn(v[j].x * inv, v[j].y * inv);
            __half2 h23 = __floats2half2_rn(v[j].z * inv, v[j].w * inv);
            uint2 pv = make_uint2(*reinterpret_cast<uint32_t*>(&h01),
                                  *reinterpret_cast<uint32_t*>(&h23));
            const uint32_t off = (uint32_t)j * 32768u + (uint32_t)mtile * 256u +
                                 (((uint32_t)lane * 8u) ^ (((uint32_t)mtile & 7u) << 4));
            *reinterpret_cast<uint2*>(gwr + off) = pv;
        }
        __threadfence();
        if (lane == 0) atomicAdd(&g_done, 1u);
    }

    // ---- tid0: mbar init, wait for all classes, then issue B bulk 0..4 ----
    if (tid == 0) {
#pragma unroll
        for (int s = 0; s < 5; s++) MBAR_INIT(sbase + MBAR_BASE + s * 8, 1);
        asm volatile("fence.proxy.async.shared::cta;" ::: "memory");
        while (ld_acq(&g_done) < (uint32_t)CDIM) { }
#pragma unroll
        for (int s = 0; s < 5; s++) {
            MBAR_EXPECT_TX(sbase + MBAR_BASE + s * 8, 32768);
            BULK_G2S(sbase + B_OFF + s * 32768, gb + (size_t)s * 32768, 32768,
                     sbase + MBAR_BASE + s * 8);
        }
    }

    // ---- convert all x -> full resident A tile ----
#pragma unroll
    for (int j = 0; j < 8; j++) {
        __half2 h01 = __floats2half2_rn(__expf(xv[j].x), __expf(xv[j].y));
        __half2 h23 = __floats2half2_rn(__expf(xv[j].z), __expf(xv[j].w));
        uint2 pv = make_uint2(*reinterpret_cast<uint32_t*>(&h01),
                              *reinterpret_cast<uint32_t*>(&h23));
        const uint32_t byteOff = (uint32_t)j * 4096u +
                                 swz256(xrow, (xc4 >> 1) * 16) + (xc4 & 1) * 8;
        *reinterpret_cast<uint2*>(smem + A_OFF + byteOff) = pv;
    }

    float acc[2][2][4];            // [parity][ni]
#pragma unroll
    for (int p = 0; p < 2; p++)
#pragma unroll
        for (int j = 0; j < 2; j++)
#pragma unroll
            for (int e = 0; e < 4; e++) acc[p][j][e] = 0.0f;

    const uint32_t aRow = (lane & 7) + ((lane >> 3) & 1) * 8;
    const uint32_t aCol = (lane >> 4) * 16;
    const uint32_t bRow = nw * 16 + ((lane >> 4) & 1) * 8 + (lane & 7);
    const uint32_t bCol = ((lane >> 3) & 1) * 16;
    uint32_t relA[8], relB[8];
#pragma unroll
    for (int ks = 0; ks < 8; ks++) {
        relA[ks] = swz256(aRow, (uint32_t)ks * 32 + aCol);
        relB[ks] = swz256(bRow, (uint32_t)ks * 32 + bCol);
    }

    __syncthreads();   // A tile + mbarriers visible

    // ---- mainloop: 4 iters per k-half ----
#pragma unroll
    for (int i = 0; i < 4; i++) {
        const int chunk = kh * 4 + i;
        int buf, parity;
        if (kh == 0) { buf = i; parity = 0; }
        else         { buf = (i == 0) ? 4 : (i - 1); parity = (i == 0) ? 0 : 1; }

        MBAR_WAIT(sbase + MBAR_BASE + buf * 8, parity);

        const uint32_t curA = sbase + A_OFF + (uint32_t)chunk * 4096u;
        const uint32_t curB = sbase + B_OFF + (uint32_t)buf * 32768u;
#pragma unroll
        for (int ks = 0; ks < 8; ks++) {
            uint32_t a[4], b[4];
            LDMATRIX_X4(a[0], a[1], a[2], a[3], curA + relA[ks]);
            LDMATRIX_X4(b[0], b[1], b[2], b[3], curB + relB[ks]);
            const int p = ks & 1;
            MMA_F16(acc[p][0], a, b);
            MMA_F16(acc[p][1], a, b + 2);
        }

        // kh0 recycles its finished buffer i for chunk 5+i
        if (kh == 0 && i < 3) {
            asm volatile("bar.sync 1, 256;" ::: "memory");   // kh0 warps only
            if (tid == 0) {
                MBAR_EXPECT_TX(sbase + MBAR_BASE + i * 8, 32768);
                BULK_G2S(sbase + B_OFF + (uint32_t)i * 32768u,
                         gb + (size_t)(5 + i) * 32768, 32768,
                         sbase + MBAR_BASE + i * 8);
            }
        }
    }

    // ---- reduction: kh1 publishes, kh0 combines + log + store ----
    float s[2][4];
#pragma unroll
    for (int j = 0; j < 2; j++)
#pragma unroll
        for (int e = 0; e < 4; e++) s[j][e] = acc[0][j][e] + acc[1][j][e];

    float* red = reinterpret_cast<float*>(smem + RED_OFF);
    const uint32_t r0 = lane >> 2;
    const uint32_t cb = (lane & 3) * 2;
    if (kh == 1) {
        float* dst = red + (size_t)nw * 256;
#pragma unroll
        for (int ni = 0; ni < 2; ni++) {
            const uint32_t c = ni * 8 + cb;
            *reinterpret_cast<float2*>(dst + r0 * 16 + c)       = make_float2(s[ni][0], s[ni][1]);
            *reinterpret_cast<float2*>(dst + (r0 + 8) * 16 + c) = make_float2(s[ni][2], s[ni][3]);
        }
    }
    __syncthreads();
    if (kh == 0) {
        const float* src = red + (size_t)nw * 256;
#pragma unroll
        for (int ni = 0; ni < 2; ni++) {
            const uint32_t c = ni * 8 + cb;
            float2 v0 = *reinterpret_cast<const float2*>(src + r0 * 16 + c);
            float2 v1 = *reinterpret_cast<const float2*>(src + (r0 + 8) * 16 + c);
            const float t0 = s[ni][0] + v0.x;
            const float t1 = s[ni][1] + v0.y;
            const float t2 = s[ni][2] + v1.x;
            const float t3 = s[ni][3] + v1.y;
            const int m = mtile * BM + (int)r0;
            const int n = nw * 16 + ni * 8 + (int)cb;
            *reinterpret_cast<float2*>(out + (size_t)m * CDIM + n) =
                make_float2(__logf(t0), __logf(t1));
            *reinterpret_cast<float2*>(out + (size_t)(m + 8) * CDIM + n) =
                make_float2(__logf(t2), __logf(t3));
        }
    }

    // ---- replay-safe counter reset: last exiting CTA zeroes both ----
    if (tid == 0) {
        __threadfence();
        const uint32_t v = atomicAdd(&g_exit, 1u);
        if (v == (uint32_t)(BDIM / BM) - 1u) {
            atomicExch(&g_done, 0u);
            atomicExch(&g_exit, 0u);
        }
    }
}

// ---------------------------------------------------------------------------
extern "C" void kernel_launch(void* const* d_in, const int* in_sizes, int n_in,
                              void* d_out, int out_size) {
    const float* x = (const float*)d_in[0];
    const float* w = (const float*)d_in[1];
    if (n_in >= 2 && in_sizes[0] == CDIM * FDIM && in_sizes[1] == BDIM * FDIM) {
        w = (const float*)d_in[0];
        x = (const float*)d_in[1];
    }
    float* out = (float*)d_out;

    static bool attr_set = false;
    if (!attr_set) {
        cudaFuncSetAttribute(fused_kernel, cudaFuncAttributeMaxDynamicSharedMemorySize, SMEM_TOTAL);
        attr_set = true;
    }

    fused_kernel<<<BDIM / BM, THREADS, SMEM_TOTAL>>>(x, w, out);
}

// round 17
// speedup vs baseline: 1.0104x; 1.0104x over previous
#include <cuda_runtime.h>
#include <cuda_fp16.h>
#include <cstdint>

// Problem dims (fixed)
#define FDIM 1024
#define CDIM 128
#define BDIM 2048

#define BM 16
#define BN 128
#define THREADS 512

// ---------------- scratch ----------------
// Blocked, pre-swizzled: byte offset = kc*32768 + c*256 + ((kk*2) ^ ((c&7)<<4))
__device__ __align__(16) __half g_b[CDIM * FDIM];

// ---------------- helpers ----------------
__device__ __forceinline__ uint32_t smem_u32(const void* p) {
    uint32_t a;
    asm("{ .reg .u64 t; cvta.to.shared.u64 t, %1; cvt.u32.u64 %0, t; }" : "=r"(a) : "l"(p));
    return a;
}
__device__ __forceinline__ uint32_t swz256(uint32_t row, uint32_t colByte) {
    return row * 256u + (colByte ^ ((row & 7u) << 4));
}

#define MBAR_INIT(mb, n)  asm volatile("mbarrier.init.shared.b64 [%0], %1;" :: "r"((uint32_t)(mb)), "r"((uint32_t)(n)) : "memory")
#define MBAR_EXPECT_TX(mb, bytes) \
    asm volatile("mbarrier.arrive.expect_tx.shared.b64 _, [%0], %1;" :: "r"((uint32_t)(mb)), "r"((uint32_t)(bytes)) : "memory")
#define BULK_G2S(dst, src, bytes, mb) \
    asm volatile("cp.async.bulk.shared::cta.global.mbarrier::complete_tx::bytes [%0], [%1], %2, [%3];" \
                 :: "r"((uint32_t)(dst)), "l"(src), "r"((uint32_t)(bytes)), "r"((uint32_t)(mb)) : "memory")
#define MBAR_WAIT(mb, ph) do {                                                   \
    uint32_t _m = (uint32_t)(mb), _p = (uint32_t)(ph), _d;                       \
    asm volatile("{\n\t.reg .pred p;\n\t"                                        \
        "mbarrier.try_wait.parity.acquire.cta.shared::cta.b64 p, [%1], %2;\n\t"  \
        "selp.b32 %0, 1, 0, p;\n\t}" : "=r"(_d) : "r"(_m), "r"(_p) : "memory");  \
    if (!_d) {                                                                   \
        asm volatile("{\n\t.reg .pred P1;\n\t"                                   \
            "W_%=:\n\t"                                                          \
            "mbarrier.try_wait.parity.acquire.cta.shared::cta.b64 P1, [%0], %1, 0x989680;\n\t" \
            "@P1 bra.uni D_%=;\n\t"                                              \
            "bra.uni W_%=;\n\t"                                                  \
            "D_%=:\n\t}" :: "r"(_m), "r"(_p) : "memory");                        \
    }                                                                            \
} while (0)

#define LDMATRIX_X4(r0, r1, r2, r3, addr)                                        \
    asm volatile("ldmatrix.sync.aligned.m8n8.x4.shared.b16 {%0,%1,%2,%3}, [%4];" \
                 : "=r"(r0), "=r"(r1), "=r"(r2), "=r"(r3) : "r"(addr))

#define MMA_F16(d, a, b)                                                         \
    asm volatile("mma.sync.aligned.m16n8k16.row.col.f32.f16.f16.f32 "            \
                 "{%0,%1,%2,%3}, {%4,%5,%6,%7}, {%8,%9}, {%0,%1,%2,%3};"         \
                 : "+f"((d)[0]), "+f"((d)[1]), "+f"((d)[2]), "+f"((d)[3])        \
                 : "r"((a)[0]), "r"((a)[1]), "r"((a)[2]), "r"((a)[3]),           \
                   "r"((b)[0]), "r"((b)[1]))

// ---------------------------------------------------------------------------
// Kernel 1: warp-per-class softmax(weight) -> blocked+pre-swizzled g_b.
// ---------------------------------------------------------------------------
__global__ void __launch_bounds__(256) prep_w_kernel(const float* __restrict__ w) {
    const int c    = (blockIdx.x * 256 + threadIdx.x) >> 5;   // class 0..127
    const int lane = threadIdx.x & 31;
    const float* row = w + (size_t)c * FDIM;

    float4 v[8];
    float m = -1e30f;
#pragma unroll
    for (int j = 0; j < 8; j++) {
        v[j] = *reinterpret_cast<const float4*>(row + j * 128 + lane * 4);
        m = fmaxf(m, fmaxf(fmaxf(v[j].x, v[j].y), fmaxf(v[j].z, v[j].w)));
    }
#pragma unroll
    for (int s = 16; s > 0; s >>= 1) m = fmaxf(m, __shfl_xor_sync(0xffffffffu, m, s));

    float sum = 0.0f;
#pragma unroll
    for (int j = 0; j < 8; j++) {
        v[j].x = __expf(v[j].x - m); v[j].y = __expf(v[j].y - m);
        v[j].z = __expf(v[j].z - m); v[j].w = __expf(v[j].w - m);
        sum += (v[j].x + v[j].y) + (v[j].z + v[j].w);
    }
#pragma unroll
    for (int s = 16; s > 0; s >>= 1) sum += __shfl_xor_sync(0xffffffffu, sum, s);
    const float inv = 1.0f / sum;

    char* gbase = reinterpret_cast<char*>(g_b);
#pragma unroll
    for (int j = 0; j < 8; j++) {
        __half2 h01 = __floats2half2_rn(v[j].x * inv, v[j].y * inv);
        __half2 h23 = __floats2half2_rn(v[j].z * inv, v[j].w * inv);
        uint2 pv = make_uint2(*reinterpret_cast<uint32_t*>(&h01),
                              *reinterpret_cast<uint32_t*>(&h23));
        const uint32_t off = (uint32_t)j * 32768u + (uint32_t)c * 256u +
                             (((uint32_t)lane * 8u) ^ (((uint32_t)c & 7u) << 4));
        *reinterpret_cast<uint2*>(gbase + off) = pv;
    }
}

// ---------------------------------------------------------------------------
// Kernel 2: pipelined-conversion, resident-A, K-half-split HMMA GEMM.
// 128 CTAs x 512 threads. kh = warp>>3, nw = warp&7 (warp tile 16x16).
// Prologue: 8 x-LDG (max MLP), B bulks 0..4 issued, convert only chunks
// {0,4}. Iter i: MMA chunk -> convert {i+1, i+5} -> syncthreads -> recycle
// buf i for chunk 5+i. kh1 publishes partials; kh0 reduces + log + stores.
// ---------------------------------------------------------------------------
#define MBAR_BASE 0                 // 5 x 8B mbarriers
#define A_OFF 1024                  // 32KB full A (8 chunks x 4KB)
#define B_OFF (A_OFF + 32768)       // 5 x 32KB B buffers
#define RED_OFF (B_OFF + 5 * 32768) // 8KB reduce buffer
#define SMEM_TOTAL (RED_OFF + 8192) // 205824

__device__ __forceinline__ void convert_chunk(char* smem, const float4 v,
                                              uint32_t chunk, uint32_t xrow, uint32_t xc4) {
    __half2 h01 = __floats2half2_rn(__expf(v.x), __expf(v.y));
    __half2 h23 = __floats2half2_rn(__expf(v.z), __expf(v.w));
    uint2 pv = make_uint2(*reinterpret_cast<uint32_t*>(&h01),
                          *reinterpret_cast<uint32_t*>(&h23));
    const uint32_t byteOff = chunk * 4096u +
                             swz256(xrow, (xc4 >> 1) * 16) + (xc4 & 1) * 8;
    *reinterpret_cast<uint2*>(smem + A_OFF + byteOff) = pv;
}

__global__ void __launch_bounds__(THREADS) mma_kernel(const float* __restrict__ x,
                                                      float* __restrict__ out) {
    extern __shared__ char smem[];
    const uint32_t sbase = smem_u32(smem);
    const int tid  = threadIdx.x;
    const int warp = tid >> 5;
    const int lane = tid & 31;
    const int kh   = warp >> 3;    // 0: chunks 0-3, 1: chunks 4-7
    const int nw   = warp & 7;     // cols [nw*16, +16)

    const int mtile = (int)blockIdx.x;   // 0..127
    const char* gb = reinterpret_cast<const char*>(g_b);

    // ---- FIRST: all x loads, maximal MLP ----
    const float* xbase = x + (size_t)mtile * BM * FDIM;
    const uint32_t xrow = (uint32_t)tid >> 5;    // 0..15
    const uint32_t xc4  = (uint32_t)tid & 31;
    float4 xv[8];
#pragma unroll
    for (int j = 0; j < 8; j++)
        xv[j] = *reinterpret_cast<const float4*>(
            xbase + (size_t)xrow * FDIM + j * 128 + xc4 * 4);

    // ---- mbar init + B bulk for chunks 0..4 (independent of conversions) ----
    if (tid == 0) {
#pragma unroll
        for (int s = 0; s < 5; s++) MBAR_INIT(sbase + MBAR_BASE + s * 8, 1);
        asm volatile("fence.proxy.async.shared::cta;" ::: "memory");
#pragma unroll
        for (int s = 0; s < 5; s++) {
            MBAR_EXPECT_TX(sbase + MBAR_BASE + s * 8, 32768);
            BULK_G2S(sbase + B_OFF + s * 32768, gb + (size_t)s * 32768, 32768,
                     sbase + MBAR_BASE + s * 8);
        }
    }

    // ---- convert ONLY chunks 0 and 4 (first chunk of each k-half) ----
    convert_chunk(smem, xv[0], 0, xrow, xc4);
    convert_chunk(smem, xv[4], 4, xrow, xc4);

    float acc[2][2][4];            // [parity][ni]
#pragma unroll
    for (int p = 0; p < 2; p++)
#pragma unroll
        for (int j = 0; j < 2; j++)
#pragma unroll
            for (int e = 0; e < 4; e++) acc[p][j][e] = 0.0f;

    const uint32_t aRow = (lane & 7) + ((lane >> 3) & 1) * 8;
    const uint32_t aCol = (lane >> 4) * 16;
    const uint32_t bRow = nw * 16 + ((lane >> 4) & 1) * 8 + (lane & 7);
    const uint32_t bCol = ((lane >> 3) & 1) * 16;
    uint32_t relA[8], relB[8];
#pragma unroll
    for (int ks = 0; ks < 8; ks++) {
        relA[ks] = swz256(aRow, (uint32_t)ks * 32 + aCol);
        relB[ks] = swz256(bRow, (uint32_t)ks * 32 + bCol);
    }

    __syncthreads();   // chunks {0,4} + mbarriers visible

    // ---- mainloop: 4 iters per k-half, conversion pipelined in ----
#pragma unroll
    for (int i = 0; i < 4; i++) {
        const int chunk = kh * 4 + i;
        int buf, parity;
        if (kh == 0) { buf = i; parity = 0; }
        else         { buf = (i == 0) ? 4 : (i - 1); parity = (i == 0) ? 0 : 1; }

        MBAR_WAIT(sbase + MBAR_BASE + buf * 8, parity);

        const uint32_t curA = sbase + A_OFF + (uint32_t)chunk * 4096u;
        const uint32_t curB = sbase + B_OFF + (uint32_t)buf * 32768u;
#pragma unroll
        for (int ks = 0; ks < 8; ks++) {
            uint32_t a[4], b[4];
            LDMATRIX_X4(a[0], a[1], a[2], a[3], curA + relA[ks]);
            LDMATRIX_X4(b[0], b[1], b[2], b[3], curB + relB[ks]);
            const int p = ks & 1;
            MMA_F16(acc[p][0], a, b);
            MMA_F16(acc[p][1], a, b + 2);
        }

        if (i < 3) {
            // convert next chunks for both halves (from registers in flight)
            convert_chunk(smem, xv[i + 1], (uint32_t)(i + 1), xrow, xc4);
            convert_chunk(smem, xv[i + 5], (uint32_t)(i + 5), xrow, xc4);
            __syncthreads();   // conversions + buf-i reads complete
            if (tid == 0) {    // recycle buf i -> chunk 5+i (kh1 iter i+1)
                MBAR_EXPECT_TX(sbase + MBAR_BASE + i * 8, 32768);
                BULK_G2S(sbase + B_OFF + (uint32_t)i * 32768u,
                         gb + (size_t)(5 + i) * 32768, 32768,
                         sbase + MBAR_BASE + i * 8);
            }
        }
    }

    // ---- reduction: kh1 publishes, kh0 combines + log + store ----
    float s[2][4];
#pragma unroll
    for (int j = 0; j < 2; j++)
#pragma unroll
        for (int e = 0; e < 4; e++) s[j][e] = acc[0][j][e] + acc[1][j][e];

    float* red = reinterpret_cast<float*>(smem + RED_OFF);
    const uint32_t r0 = lane >> 2;
    const uint32_t cb = (lane & 3) * 2;
    if (kh == 1) {
        float* dst = red + (size_t)nw * 256;
#pragma unroll
        for (int ni = 0; ni < 2; ni++) {
            const uint32_t c = ni * 8 + cb;
            *reinterpret_cast<float2*>(dst + r0 * 16 + c)       = make_float2(s[ni][0], s[ni][1]);
            *reinterpret_cast<float2*>(dst + (r0 + 8) * 16 + c) = make_float2(s[ni][2], s[ni][3]);
        }
    }
    __syncthreads();
    if (kh == 0) {
        const float* src = red + (size_t)nw * 256;
#pragma unroll
        for (int ni = 0; ni < 2; ni++) {
            const uint32_t c = ni * 8 + cb;
            float2 v0 = *reinterpret_cast<const float2*>(src + r0 * 16 + c);
            float2 v1 = *reinterpret_cast<const float2*>(src + (r0 + 8) * 16 + c);
            const float t0 = s[ni][0] + v0.x;
            const float t1 = s[ni][1] + v0.y;
            const float t2 = s[ni][2] + v1.x;
            const float t3 = s[ni][3] + v1.y;
            const int m = mtile * BM + (int)r0;
            const int n = nw * 16 + ni * 8 + (int)cb;
            *reinterpret_cast<float2*>(out + (size_t)m * CDIM + n) =
                make_float2(__logf(t0), __logf(t1));
            *reinterpret_cast<float2*>(out + (size_t)(m + 8) * CDIM + n) =
                make_float2(__logf(t2), __logf(t3));
        }
    }
}

// ---------------------------------------------------------------------------
extern "C" void kernel_launch(void* const* d_in, const int* in_sizes, int n_in,
                              void* d_out, int out_size) {
    const float* x = (const float*)d_in[0];
    const float* w = (const float*)d_in[1];
    if (n_in >= 2 && in_sizes[0] == CDIM * FDIM && in_sizes[1] == BDIM * FDIM) {
        w = (const float*)d_in[0];
        x = (const float*)d_in[1];
    }
    float* out = (float*)d_out;

    static bool attr_set = false;
    if (!attr_set) {
        cudaFuncSetAttribute(mma_kernel, cudaFuncAttributeMaxDynamicSharedMemorySize, SMEM_TOTAL);
        attr_set = true;
    }

    prep_w_kernel<<<CDIM / 8, 256>>>(w);
    mma_kernel<<<BDIM / BM, THREADS, SMEM_TOTAL>>>(x, out);
}